// round 2
// baseline (speedup 1.0000x reference)
#include <cuda_runtime.h>
#include <cstdint>

#define NB   16
#define CIN  256
#define CR   64
#define HWSZ 2304
#define NJT  18            // 2304 / 128 column tiles
#define NIT  36            // 2304 / 64  row tiles

// Scratch (device globals: no allocation allowed)
__device__ float g_q[NB*CR*HWSZ];
__device__ float g_k[NB*CR*HWSZ];
__device__ float g_v[NB*CR*HWSZ];
__device__ float g_att[NB*CR*HWSZ];
__device__ float g_partial[NB*NJT];

// ---------------------------------------------------------------------------
// Kernel 1: QKV projection.  out[n,c,p] = sum_ci W[c,ci] * x[n,ci,p] + b[c]
// Grid: (18 j-tiles, 16 batches, 3 {q,k,v}); 256 threads; tile 64x128, BK=32.
// ---------------------------------------------------------------------------
__global__ __launch_bounds__(256) void qkv_kernel(
    const float* __restrict__ x,
    const float* __restrict__ Wq, const float* __restrict__ bq,
    const float* __restrict__ Wk, const float* __restrict__ bk,
    const float* __restrict__ Wv, const float* __restrict__ bv)
{
    __shared__ float sW[32*68];    // [k][c], padded stride 68
    __shared__ float sX[32*128];   // [k][j]

    const int tid = threadIdx.x;
    const int tx = tid & 15, ty = tid >> 4;
    const int n  = blockIdx.y;
    const int j0 = blockIdx.x * 128;
    const int which = blockIdx.z;

    const float* W = (which == 0) ? Wq : (which == 1) ? Wk : Wv;
    const float* b = (which == 0) ? bq : (which == 1) ? bk : bv;
    float* out = (which == 0) ? g_q : (which == 1) ? g_k : g_v;

    float acc[4][8];
    #pragma unroll
    for (int i = 0; i < 4; i++)
        #pragma unroll
        for (int j = 0; j < 8; j++) acc[i][j] = 0.f;

    for (int kk = 0; kk < CIN; kk += 32) {
        // W tile: 64 c x 32 k, transposed into sW[k][c]
        for (int t = tid; t < 64*32; t += 256) {
            int c = t >> 5, k = t & 31;
            sW[k*68 + c] = W[c*CIN + kk + k];
        }
        // X tile: 32 k x 128 j (float4)
        for (int t = tid; t < 32*32; t += 256) {
            int k = t >> 5, jf = t & 31;
            *(float4*)&sX[k*128 + jf*4] =
                *(const float4*)&x[((size_t)n*CIN + kk + k)*HWSZ + j0 + jf*4];
        }
        __syncthreads();

        #pragma unroll 8
        for (int k = 0; k < 32; k++) {
            float4 w4 = *(float4*)&sW[k*68 + ty*4];
            float4 xa = *(float4*)&sX[k*128 + tx*8];
            float4 xb = *(float4*)&sX[k*128 + tx*8 + 4];
            float wv[4] = {w4.x, w4.y, w4.z, w4.w};
            float xv[8] = {xa.x, xa.y, xa.z, xa.w, xb.x, xb.y, xb.z, xb.w};
            #pragma unroll
            for (int i = 0; i < 4; i++)
                #pragma unroll
                for (int j = 0; j < 8; j++)
                    acc[i][j] = fmaf(wv[i], xv[j], acc[i][j]);
        }
        __syncthreads();
    }

    #pragma unroll
    for (int cc = 0; cc < 4; cc++) {
        int c = ty*4 + cc;
        float bb = b[c];
        float4 r0 = make_float4(acc[cc][0]+bb, acc[cc][1]+bb, acc[cc][2]+bb, acc[cc][3]+bb);
        float4 r1 = make_float4(acc[cc][4]+bb, acc[cc][5]+bb, acc[cc][6]+bb, acc[cc][7]+bb);
        size_t base = ((size_t)n*CR + c)*HWSZ + j0 + tx*8;
        *(float4*)&out[base]     = r0;
        *(float4*)&out[base + 4] = r1;
    }
}

// ---------------------------------------------------------------------------
// Kernel 2: fused attention.  For a 128-column tile of Q:
//   loop 64-row tiles of K,V:  P = exp(K_tile^T Q_tile);  A += V_tile * P
// Also accumulates per-block sum of exp -> g_partial (deterministic).
// Grid: (18, 16); 256 threads; ~97 KB dynamic smem; 2 blocks/SM.
// ---------------------------------------------------------------------------
__global__ __launch_bounds__(256, 2) void attn_kernel()
{
    extern __shared__ float sm[];
    float* sQ  = sm;                 // 64 x 128
    float* sK  = sQ  + 64*128;       // 64 x 64
    float* sVt = sK  + 64*64;        // 64 x 68  (transposed, padded)
    float* sP  = sVt + 64*68;        // 64 x 128

    const int tid = threadIdx.x;
    const int tx = tid & 15, ty = tid >> 4;
    const int n  = blockIdx.y;
    const int j0 = blockIdx.x * 128;

    // Q tile: loaded once, reused for all 36 K/V tiles
    for (int t = tid; t < 64*32; t += 256) {
        int c = t >> 5, jf = t & 31;
        *(float4*)&sQ[c*128 + jf*4] =
            *(const float4*)&g_q[((size_t)n*CR + c)*HWSZ + j0 + jf*4];
    }

    float acc[4][8];
    #pragma unroll
    for (int i = 0; i < 4; i++)
        #pragma unroll
        for (int j = 0; j < 8; j++) acc[i][j] = 0.f;
    float lsum = 0.f;

    for (int it = 0; it < NIT; it++) {
        const int i0 = it * 64;
        // K tile [c][i]
        for (int t = tid; t < 64*16; t += 256) {
            int c = t >> 4, f = t & 15;
            *(float4*)&sK[c*64 + f*4] =
                *(const float4*)&g_k[((size_t)n*CR + c)*HWSZ + i0 + f*4];
        }
        // V tile transposed: sVt[i][c]
        for (int t = tid; t < 64*64; t += 256) {
            int c = t >> 6, i = t & 63;
            sVt[i*68 + c] = g_v[((size_t)n*CR + c)*HWSZ + i0 + i];
        }
        __syncthreads();

        // Phase 1: P[i,j] = sum_c K[c,i]*Q[c,j]
        float p[4][8];
        #pragma unroll
        for (int i = 0; i < 4; i++)
            #pragma unroll
            for (int j = 0; j < 8; j++) p[i][j] = 0.f;

        #pragma unroll 8
        for (int c = 0; c < 64; c++) {
            float4 k4 = *(float4*)&sK[c*64 + ty*4];
            float4 qa = *(float4*)&sQ[c*128 + tx*8];
            float4 qb = *(float4*)&sQ[c*128 + tx*8 + 4];
            float kv[4] = {k4.x, k4.y, k4.z, k4.w};
            float qv[8] = {qa.x, qa.y, qa.z, qa.w, qb.x, qb.y, qb.z, qb.w};
            #pragma unroll
            for (int i = 0; i < 4; i++)
                #pragma unroll
                for (int j = 0; j < 8; j++)
                    p[i][j] = fmaf(kv[i], qv[j], p[i][j]);
        }

        // exp + local sum + stage P to smem
        #pragma unroll
        for (int i = 0; i < 4; i++) {
            #pragma unroll
            for (int j = 0; j < 8; j++) {
                float e = __expf(p[i][j]);
                lsum += e;
                p[i][j] = e;
            }
            *(float4*)&sP[(ty*4+i)*128 + tx*8]     = make_float4(p[i][0], p[i][1], p[i][2], p[i][3]);
            *(float4*)&sP[(ty*4+i)*128 + tx*8 + 4] = make_float4(p[i][4], p[i][5], p[i][6], p[i][7]);
        }
        __syncthreads();

        // Phase 2: A[c,j] += sum_i V[c,i] * P[i,j]
        #pragma unroll 8
        for (int i = 0; i < 64; i++) {
            float4 v4 = *(float4*)&sVt[i*68 + ty*4];
            float4 pa = *(float4*)&sP[i*128 + tx*8];
            float4 pb = *(float4*)&sP[i*128 + tx*8 + 4];
            float vv[4] = {v4.x, v4.y, v4.z, v4.w};
            float pv[8] = {pa.x, pa.y, pa.z, pa.w, pb.x, pb.y, pb.z, pb.w};
            #pragma unroll
            for (int c = 0; c < 4; c++)
                #pragma unroll
                for (int j = 0; j < 8; j++)
                    acc[c][j] = fmaf(vv[c], pv[j], acc[c][j]);
        }
        __syncthreads();
    }

    // Write unnormalized A
    #pragma unroll
    for (int cc = 0; cc < 4; cc++) {
        int c = ty*4 + cc;
        size_t base = ((size_t)n*CR + c)*HWSZ + j0 + tx*8;
        *(float4*)&g_att[base]     = make_float4(acc[cc][0], acc[cc][1], acc[cc][2], acc[cc][3]);
        *(float4*)&g_att[base + 4] = make_float4(acc[cc][4], acc[cc][5], acc[cc][6], acc[cc][7]);
    }

    // Block-level sum of exp (deterministic; no atomics)
    #pragma unroll
    for (int off = 16; off > 0; off >>= 1)
        lsum += __shfl_xor_sync(0xFFFFFFFFu, lsum, off);
    if ((tid & 31) == 0) sK[tid >> 5] = lsum;   // sK reusable after last sync
    __syncthreads();
    if (tid == 0) {
        float s = 0.f;
        #pragma unroll
        for (int w = 0; w < 8; w++) s += sK[w];
        g_partial[n*NJT + blockIdx.x] = s;
    }
}

// ---------------------------------------------------------------------------
// Kernel 3: out[n,o,p] = g * (Watt[o,:] @ (A[:,p]/S[n]) + batt[o]) + g
// Grid: (36 j-tiles of 64, 4 o-tiles of 64, 16 batches); 256 threads.
// ---------------------------------------------------------------------------
__global__ __launch_bounds__(256) void out_kernel(
    const float* __restrict__ gco,
    const float* __restrict__ Watt, const float* __restrict__ batt,
    float* __restrict__ out)
{
    __shared__ float sW[64*68];   // [k][o], padded
    __shared__ float sA[64*68];   // [k][j], padded
    __shared__ float sS;

    const int tid = threadIdx.x;
    const int tx = tid & 15, ty = tid >> 4;
    const int n  = blockIdx.z;
    const int o0 = blockIdx.y * 64;
    const int j0 = blockIdx.x * 64;

    if (tid == 0) {
        float s = 0.f;
        #pragma unroll
        for (int t = 0; t < NJT; t++) s += g_partial[n*NJT + t];
        sS = s;
    }
    for (int t = tid; t < 64*64; t += 256) {
        int o = t >> 6, k = t & 63;
        sW[k*68 + o] = Watt[(size_t)(o0 + o)*CR + k];
    }
    for (int t = tid; t < 64*64; t += 256) {
        int c = t >> 6, j = t & 63;
        sA[c*68 + j] = g_att[((size_t)n*CR + c)*HWSZ + j0 + j];
    }
    __syncthreads();

    float acc[4][4];
    #pragma unroll
    for (int i = 0; i < 4; i++)
        #pragma unroll
        for (int j = 0; j < 4; j++) acc[i][j] = 0.f;

    #pragma unroll 8
    for (int k = 0; k < 64; k++) {
        float4 w4 = *(float4*)&sW[k*68 + ty*4];
        float4 a4 = *(float4*)&sA[k*68 + tx*4];
        float wv[4] = {w4.x, w4.y, w4.z, w4.w};
        float av[4] = {a4.x, a4.y, a4.z, a4.w};
        #pragma unroll
        for (int i = 0; i < 4; i++)
            #pragma unroll
            for (int j = 0; j < 4; j++)
                acc[i][j] = fmaf(wv[i], av[j], acc[i][j]);
    }

    const float invS = 1.f / sS;
    #pragma unroll
    for (int oi = 0; oi < 4; oi++) {
        int o = o0 + ty*4 + oi;
        float bias = batt[o];
        size_t base = ((size_t)n*CIN + o)*HWSZ + j0 + tx*4;
        float4 g = *(const float4*)&gco[base];
        float4 r;
        r.x = g.x * (fmaf(acc[oi][0], invS, bias) + 1.f);
        r.y = g.y * (fmaf(acc[oi][1], invS, bias) + 1.f);
        r.z = g.z * (fmaf(acc[oi][2], invS, bias) + 1.f);
        r.w = g.w * (fmaf(acc[oi][3], invS, bias) + 1.f);
        *(float4*)&out[base] = r;
    }
}

// ---------------------------------------------------------------------------
extern "C" void kernel_launch(void* const* d_in, const int* in_sizes, int n_in,
                              void* d_out, int out_size)
{
    const float* x    = (const float*)d_in[0];   // feature_maps [16,256,48,48]
    const float* gco  = (const float*)d_in[1];   // global_channel_output
    const float* Wq   = (const float*)d_in[2];
    const float* bq   = (const float*)d_in[3];
    const float* Wk   = (const float*)d_in[4];
    const float* bk   = (const float*)d_in[5];
    const float* Wv   = (const float*)d_in[6];
    const float* bv   = (const float*)d_in[7];
    const float* Watt = (const float*)d_in[8];
    const float* batt = (const float*)d_in[9];
    float* out = (float*)d_out;

    const int smem2 = (64*128 + 64*64 + 64*68 + 64*128) * 4;  // 99328 B
    cudaFuncSetAttribute(attn_kernel, cudaFuncAttributeMaxDynamicSharedMemorySize, smem2);

    qkv_kernel<<<dim3(NJT, NB, 3), 256>>>(x, Wq, bq, Wk, bk, Wv, bv);
    attn_kernel<<<dim3(NJT, NB), 256, smem2>>>();
    out_kernel<<<dim3(NIT, 4, NB), 256>>>(gco, Watt, batt, out);
}